// round 4
// baseline (speedup 1.0000x reference)
#include <cuda_runtime.h>

#define ELN 512
#define NIMG 128
#define BIMG 64
#define IMG_PIX (ELN*ELN)
#define PI_F 3.14159265358979f

// Scratch (device globals: allocation-free per harness rules)
__device__ float2 g_bufA[(size_t)NIMG * IMG_PIX];   // 256 MB
__device__ float2 g_bufB[(size_t)NIMG * IMG_PIX];   // 256 MB
__device__ float  g_ac[(size_t)NIMG * IMG_PIX];     // 128 MB
__device__ unsigned int g_mm[2 * NIMG];             // per-image (min,max) encoded
__device__ double g_diff;

// ---- monotone float <-> uint encoding for atomic min/max ----
__device__ __forceinline__ unsigned fenc(float f) {
    unsigned u = __float_as_uint(f);
    return (u & 0x80000000u) ? ~u : (u | 0x80000000u);
}
__device__ __forceinline__ float fdec(unsigned e) {
    return __uint_as_float((e & 0x80000000u) ? (e ^ 0x80000000u) : ~e);
}

// ---- 512-pt Stockham radix-2 FFT in shared memory, 128 threads ----
// input in s0, output in s1. sgn = -1 forward, +1 inverse (unscaled).
__device__ __forceinline__ void fft512(float2* s0, float2* s1, int tid, float sgn) {
    float2* src = s0;
    float2* dst = s1;
    int l = 256, m = 1;
#pragma unroll
    for (int st = 0; st < 9; st++) {
        __syncthreads();
#pragma unroll
        for (int q = 0; q < 2; q++) {
            int i = tid + q * 128;        // butterfly index 0..255
            int j = i / m;                // 0..l-1
            int k = i - j * m;            // 0..m-1
            float2 c0 = src[i];
            float2 c1 = src[i + 256];
            float wi, wr;
            __sincosf(sgn * PI_F * (float)j / (float)l, &wi, &wr);
            float dx = c0.x - c1.x, dy = c0.y - c1.y;
            dst[k + 2 * j * m]     = make_float2(c0.x + c1.x, c0.y + c1.y);
            dst[k + 2 * j * m + m] = make_float2(wr * dx - wi * dy, wr * dy + wi * dx);
        }
        float2* t = src; src = dst; dst = t;
        l >>= 1; m <<= 1;
    }
    __syncthreads();
    // 9 stages (odd) -> result resides in s1
}

// ---- init accumulators each launch (graph-replay safe) ----
__global__ void k_init() {
    int i = threadIdx.x;
    if (i < NIMG) { g_mm[2 * i] = 0xFFFFFFFFu; g_mm[2 * i + 1] = 0u; }
    if (i == 0) g_diff = 0.0;
}

// ---- K1: mf0 + forward FFT along x. out: g_bufA[b][y][kx] ----
__global__ __launch_bounds__(128) void k_fwd_x(const float* __restrict__ in0,
                                               const float* __restrict__ in1) {
    __shared__ float2 s0[ELN], s1[ELN];
    int row = blockIdx.x, img = blockIdx.y, tid = threadIdx.x;
    const float* src = (img < BIMG) ? (in0 + (size_t)img * IMG_PIX)
                                    : (in1 + (size_t)(img - BIMG) * IMG_PIX);
    const float* rp = src + (size_t)row * ELN;
#pragma unroll
    for (int c = tid; c < ELN; c += 128) {
        float x = rp[c];
        s0[c] = make_float2(__expf(-8.0f * x * x), 0.0f);   // exp(-x^2/(2*0.25^2))
    }
    fft512(s0, s1, tid, -1.0f);
    float2* out = g_bufA + (size_t)img * IMG_PIX + (size_t)row * ELN;
#pragma unroll
    for (int c = tid; c < ELN; c += 128) out[c] = s1[c];
}

// ---- transpose 512x512 float2, A -> B, per image ----
__global__ void k_transpose() {
    __shared__ float2 tile[32][33];
    int img = blockIdx.z;
    const float2* ip = g_bufA + (size_t)img * IMG_PIX;
    float2*       op = g_bufB + (size_t)img * IMG_PIX;
    int x  = blockIdx.x * 32 + threadIdx.x;
    int y0 = blockIdx.y * 32;
#pragma unroll
    for (int dy = threadIdx.y; dy < 32; dy += 8)
        tile[dy][threadIdx.x] = ip[(size_t)(y0 + dy) * ELN + x];
    __syncthreads();
    int x2 = blockIdx.y * 32 + threadIdx.x;
    int y2 = blockIdx.x * 32;
#pragma unroll
    for (int dy = threadIdx.y; dy < 32; dy += 8)
        op[(size_t)(y2 + dy) * ELN + x2] = tile[threadIdx.x][dy];
}

// ---- K3: forward FFT along y + power + inverse FFT along y (row resident).
//      in: g_bufB[b][kx][y]  out: g_bufA[b][kx][y'] ----
__global__ __launch_bounds__(128) void k_mid() {
    __shared__ float2 s0[ELN], s1[ELN];
    int row = blockIdx.x, img = blockIdx.y, tid = threadIdx.x;
    const float2* ip = g_bufB + (size_t)img * IMG_PIX + (size_t)row * ELN;
#pragma unroll
    for (int c = tid; c < ELN; c += 128) s0[c] = ip[c];
    fft512(s0, s1, tid, -1.0f);
#pragma unroll
    for (int c = tid; c < ELN; c += 128) {
        float2 v = s1[c];
        s0[c] = make_float2(v.x * v.x + v.y * v.y, 0.0f);  // |F|^2 (scale cancels)
    }
    fft512(s0, s1, tid, 1.0f);
    float2* op = g_bufA + (size_t)img * IMG_PIX + (size_t)row * ELN;
#pragma unroll
    for (int c = tid; c < ELN; c += 128) op[c] = s1[c];
}

// ---- K6: inverse FFT along x, take real, apply roll (idx XOR 256),
//      write real ac + per-image min/max atomics. in: g_bufB[b][y][kx] ----
__global__ __launch_bounds__(128) void k_inv_x() {
    __shared__ float2 s0[ELN], s1[ELN];
    __shared__ float smn[4], smx[4];
    int row = blockIdx.x, img = blockIdx.y, tid = threadIdx.x;
    const float2* ip = g_bufB + (size_t)img * IMG_PIX + (size_t)row * ELN;
#pragma unroll
    for (int c = tid; c < ELN; c += 128) s0[c] = ip[c];
    fft512(s0, s1, tid, 1.0f);

    int orow = row ^ 256;   // roll by 256 == XOR with N/2
    float* out = g_ac + (size_t)img * IMG_PIX + (size_t)orow * ELN;
    float lmin = 3.4e38f, lmax = -3.4e38f;
#pragma unroll
    for (int c = tid; c < ELN; c += 128) {
        float v = s1[c].x;
        out[c ^ 256] = v;
        lmin = fminf(lmin, v);
        lmax = fmaxf(lmax, v);
    }
#pragma unroll
    for (int off = 16; off; off >>= 1) {
        lmin = fminf(lmin, __shfl_down_sync(0xFFFFFFFFu, lmin, off));
        lmax = fmaxf(lmax, __shfl_down_sync(0xFFFFFFFFu, lmax, off));
    }
    int wid = tid >> 5, lane = tid & 31;
    if (lane == 0) { smn[wid] = lmin; smx[wid] = lmax; }
    __syncthreads();
    if (tid == 0) {
        float mn = fminf(fminf(smn[0], smn[1]), fminf(smn[2], smn[3]));
        float mx = fmaxf(fmaxf(smx[0], smx[1]), fmaxf(smx[2], smx[3]));
        atomicMin(&g_mm[2 * img],     fenc(mn));
        atomicMax(&g_mm[2 * img + 1], fenc(mx));
    }
}

// ---- K7: normalize + mask + MSE partial + write concat outputs ----
__global__ __launch_bounds__(256) void k_out(const float* __restrict__ in0,
                                             const float* __restrict__ in1,
                                             float* __restrict__ out) {
    __shared__ float red[8];
    int r = blockIdx.x, b = blockIdx.y, tid = threadIdx.x;
    float mnI = fdec(g_mm[2 * b]),          mxI = fdec(g_mm[2 * b + 1]);
    float mnT = fdec(g_mm[2 * (b + BIMG)]), mxT = fdec(g_mm[2 * (b + BIMG) + 1]);
    float sI = 1.0f / (mxI - mnI + 1e-12f);
    float sT = 1.0f / (mxT - mnT + 1e-12f);
    const float* ain = g_ac + (size_t)b * IMG_PIX + (size_t)r * ELN;
    const float* atg = g_ac + (size_t)(b + BIMG) * IMG_PIX + (size_t)r * ELN;
    const float* rin = in0 + (size_t)b * IMG_PIX + (size_t)r * ELN;
    const float* rtg = in1 + (size_t)b * IMG_PIX + (size_t)r * ELN;
    float* o1 = out + 1 + (size_t)b * (ELN * 1024) + (size_t)r * 1024;
    float* o2 = o1 + (size_t)BIMG * (ELN * 1024);
    float dy = (float)(r - 256);
    float acc = 0.0f;
#pragma unroll
    for (int c = tid; c < ELN; c += 256) {
        float dx = (float)(c - 256);
        float mask = __expf(-(dx * dx + dy * dy) * (1.0f / 800.0f)); // 2*rad^2=800
        float ia = (ain[c] - mnI) * sI * mask;
        float ta = (atg[c] - mnT) * sT * mask;
        float d = ia - ta;
        acc += d * d;
        o1[c] = rin[c];  o1[ELN + c] = ia;
        o2[c] = rtg[c];  o2[ELN + c] = ta;
    }
#pragma unroll
    for (int off = 16; off; off >>= 1)
        acc += __shfl_down_sync(0xFFFFFFFFu, acc, off);
    int wid = tid >> 5, lane = tid & 31;
    if (lane == 0) red[wid] = acc;
    __syncthreads();
    if (tid == 0) {
        float s = 0.0f;
#pragma unroll
        for (int w = 0; w < 8; w++) s += red[w];
        atomicAdd(&g_diff, (double)s);
    }
}

__global__ void k_fin(float* __restrict__ out) {
    out[0] = (float)(g_diff / (double)((size_t)BIMG * IMG_PIX));
}

extern "C" void kernel_launch(void* const* d_in, const int* in_sizes, int n_in,
                              void* d_out, int out_size) {
    const float* in0 = (const float*)d_in[0];   // input  (64,1,512,512)
    const float* in1 = (const float*)d_in[1];   // target (64,1,512,512)
    float* out = (float*)d_out;                 // [diff | input_and_ac | target_and_ac]

    k_init<<<1, 128>>>();
    k_fwd_x<<<dim3(ELN, NIMG), 128>>>(in0, in1);
    k_transpose<<<dim3(16, 16, NIMG), dim3(32, 8)>>>();
    k_mid<<<dim3(ELN, NIMG), 128>>>();
    k_transpose<<<dim3(16, 16, NIMG), dim3(32, 8)>>>();
    k_inv_x<<<dim3(ELN, NIMG), 128>>>();
    k_out<<<dim3(ELN, BIMG), 256>>>(in0, in1, out);
    k_fin<<<1, 1>>>(out);
}

// round 5
// speedup vs baseline: 1.5212x; 1.5212x over previous
#include <cuda_runtime.h>

#define ELN 512
#define NIMG 128
#define BIMG 64
#define IMG_PIX (ELN*ELN)
#define TWO_PI 6.28318530717958647692f

// Scratch (device globals, float4 for 16B-aligned vector stores)
__device__ float4 g_bufA4[(size_t)NIMG * IMG_PIX / 2];   // [img][y'][kx] complex
__device__ float4 g_bufB4[(size_t)NIMG * IMG_PIX / 2];   // [img][kx][y]  complex
__device__ float  g_ac[(size_t)NIMG * IMG_PIX];
__device__ unsigned int g_mm[2 * NIMG];
__device__ double g_diff;

#define PAD(i) ((i) + ((i) >> 3))
#define SSZ 576   // 512 + 64 pad

// ---- monotone float <-> uint encoding for atomic min/max ----
__device__ __forceinline__ unsigned fenc(float f) {
    unsigned u = __float_as_uint(f);
    return (u & 0x80000000u) ? ~u : (u | 0x80000000u);
}
__device__ __forceinline__ float fdec(unsigned e) {
    return __uint_as_float((e & 0x80000000u) ? (e ^ 0x80000000u) : ~e);
}

__device__ __forceinline__ float2 cadd(float2 a, float2 b){ return make_float2(a.x+b.x, a.y+b.y); }
__device__ __forceinline__ float2 csub(float2 a, float2 b){ return make_float2(a.x-b.x, a.y-b.y); }
__device__ __forceinline__ float2 cmul(float2 a, float2 b){
    return make_float2(fmaf(a.x, b.x, -a.y*b.y), fmaf(a.x, b.y, a.y*b.x));
}

// multiply by SGN*i
template<int SGN>
__device__ __forceinline__ float2 mul_si(float2 a){
    return (SGN > 0) ? make_float2(-a.y, a.x) : make_float2(a.y, -a.x);
}

// 8-point DFT in registers, y_q = sum_p x_p * exp(SGN*2*pi*i*p*q/8)
template<int SGN>
__device__ __forceinline__ void dft8(float2* x){
    const float C = 0.70710678118654752440f;
    const float sg = (float)SGN;
    float2 F0 = cadd(x[0], x[4]), F1 = csub(x[0], x[4]);
    float2 G0 = cadd(x[2], x[6]), G1r = mul_si<SGN>(csub(x[2], x[6]));
    float2 H0 = cadd(x[1], x[5]), H1 = csub(x[1], x[5]);
    float2 I0 = cadd(x[3], x[7]), I1r = mul_si<SGN>(csub(x[3], x[7]));
    float2 E0 = cadd(F0, G0), E2 = csub(F0, G0);
    float2 E1 = cadd(F1, G1r), E3 = csub(F1, G1r);
    float2 O0 = cadd(H0, I0), O2 = csub(H0, I0);
    float2 O1 = cadd(H1, I1r), O3 = csub(H1, I1r);
    float2 W1O = make_float2(C*(O1.x - sg*O1.y), C*(O1.y + sg*O1.x));
    float2 W2O = make_float2(-sg*O2.y, sg*O2.x);
    float2 W3O = make_float2(C*(-O3.x - sg*O3.y), C*(sg*O3.x - O3.y));
    x[0] = cadd(E0, O0);  x[4] = csub(E0, O0);
    x[1] = cadd(E1, W1O); x[5] = csub(E1, W1O);
    x[2] = cadd(E2, W2O); x[6] = csub(E2, W2O);
    x[3] = cadd(E3, W3O); x[7] = csub(E3, W3O);
}

// One Stockham radix-8 stage. 64 threads per FFT (t = 0..63). L*M = 64.
template<int SGN, int L, int M>
__device__ __forceinline__ void stage8(const float2* src, float2* dst, int t){
    float2 x[8];
#pragma unroll
    for (int p = 0; p < 8; p++) x[p] = src[PAD(t + 64*p)];
    dft8<SGN>(x);
    int j = t / M, k = t - j*M;
    if (L > 1) {
        float ang = (float)SGN * (TWO_PI / (8.0f * (float)L)) * (float)j;
        float s, c; __sincosf(ang, &s, &c);
        float2 w = make_float2(c, s), wq = w;
        x[1] = cmul(x[1], wq);
#pragma unroll
        for (int q = 2; q < 8; q++) { wq = cmul(wq, w); x[q] = cmul(x[q], wq); }
    }
    int base = k + 8*j*M;
#pragma unroll
    for (int q = 0; q < 8; q++) dst[PAD(base + q*M)] = x[q];
}

// Full 512-pt FFT: input in s0, result in s1 (natural order, unscaled).
template<int SGN>
__device__ __forceinline__ void fft512_r8(float2* s0, float2* s1, int t){
    __syncthreads();
    stage8<SGN, 64, 1>(s0, s1, t);
    __syncthreads();
    stage8<SGN, 8, 8>(s1, s0, t);
    __syncthreads();
    stage8<SGN, 1, 64>(s0, s1, t);
    __syncthreads();
}

// ---- init accumulators (graph-replay safe) ----
__global__ void k_init() {
    int i = threadIdx.x;
    if (i < NIMG) { g_mm[2*i] = 0xFFFFFFFFu; g_mm[2*i + 1] = 0u; }
    if (i == 0) g_diff = 0.0;
}

// ---- K1: mf0 + forward FFT along x, transposed write -> g_bufB [img][kx][y] ----
__global__ __launch_bounds__(256) void k_fwd_x(const float* __restrict__ in0,
                                               const float* __restrict__ in1) {
    __shared__ float2 sm[2][4][SSZ];
    int tid = threadIdx.x, f = tid >> 6, t = tid & 63;
    int g = blockIdx.x, img = blockIdx.y;
    int y0 = g * 4;
    const float* src = (img < BIMG) ? in0 + (size_t)img * IMG_PIX
                                    : in1 + (size_t)(img - BIMG) * IMG_PIX;
    const float* rp = src + (size_t)(y0 + f) * ELN;
    float2* s0 = sm[0][f]; float2* s1 = sm[1][f];
#pragma unroll
    for (int p = 0; p < 8; p++) {
        float v = rp[t + 64*p];
        s0[PAD(t + 64*p)] = make_float2(__expf(-8.0f * v * v), 0.0f);
    }
    fft512_r8<-1>(s0, s1, t);
    float2* ob = (float2*)g_bufB4 + (size_t)img * IMG_PIX;
#pragma unroll
    for (int it = 0; it < 2; it++) {
        int kx = tid + it * 256;
        float2 v0 = sm[1][0][PAD(kx)], v1 = sm[1][1][PAD(kx)];
        float2 v2 = sm[1][2][PAD(kx)], v3 = sm[1][3][PAD(kx)];
        float4* o = (float4*)(ob + (size_t)kx * ELN + y0);
        o[0] = make_float4(v0.x, v0.y, v1.x, v1.y);
        o[1] = make_float4(v2.x, v2.y, v3.x, v3.y);
    }
}

// ---- K2: fwd FFT along y + |.|^2 + inv FFT along y, transposed write with
//      y-roll -> g_bufA [img][y'][kx] ----
__global__ __launch_bounds__(256) void k_mid() {
    __shared__ float2 sm[2][4][SSZ];
    int tid = threadIdx.x, f = tid >> 6, t = tid & 63;
    int g = blockIdx.x, img = blockIdx.y;
    int kx0 = g * 4;
    const float2* ib = (const float2*)g_bufB4 + (size_t)img * IMG_PIX
                       + (size_t)(kx0 + f) * ELN;
    float2* s0 = sm[0][f]; float2* s1 = sm[1][f];
#pragma unroll
    for (int p = 0; p < 8; p++) s0[PAD(t + 64*p)] = ib[t + 64*p];
    fft512_r8<-1>(s0, s1, t);
#pragma unroll
    for (int p = 0; p < 8; p++) {
        float2 v = s1[PAD(t + 64*p)];
        s0[PAD(t + 64*p)] = make_float2(fmaf(v.x, v.x, v.y * v.y), 0.0f);
    }
    fft512_r8<1>(s0, s1, t);
    float2* ob = (float2*)g_bufA4 + (size_t)img * IMG_PIX;
#pragma unroll
    for (int it = 0; it < 2; it++) {
        int y = tid + it * 256;
        float2 v0 = sm[1][0][PAD(y)], v1 = sm[1][1][PAD(y)];
        float2 v2 = sm[1][2][PAD(y)], v3 = sm[1][3][PAD(y)];
        float4* o = (float4*)(ob + (size_t)(y ^ 256) * ELN + kx0);
        o[0] = make_float4(v0.x, v0.y, v1.x, v1.y);
        o[1] = make_float4(v2.x, v2.y, v3.x, v3.y);
    }
}

// ---- K3: inverse FFT along x, real part, x-roll, write g_ac + min/max ----
__global__ __launch_bounds__(256) void k_inv_x() {
    __shared__ float2 sm[2][4][SSZ];
    __shared__ float smn[8], smx[8];
    int tid = threadIdx.x, f = tid >> 6, t = tid & 63;
    int g = blockIdx.x, img = blockIdx.y;
    int y0 = g * 4;
    const float2* ib = (const float2*)g_bufA4 + (size_t)img * IMG_PIX
                       + (size_t)(y0 + f) * ELN;
    float2* s0 = sm[0][f]; float2* s1 = sm[1][f];
#pragma unroll
    for (int p = 0; p < 8; p++) s0[PAD(t + 64*p)] = ib[t + 64*p];
    fft512_r8<1>(s0, s1, t);

    float* ob = g_ac + (size_t)img * IMG_PIX;
    float lmin = 3.4e38f, lmax = -3.4e38f;
#pragma unroll
    for (int it = 0; it < 8; it++) {
        int idx = tid + it * 256;       // 0..2047
        int ff = idx >> 9, x = idx & 511;
        float v = sm[1][ff][PAD(x)].x;
        ob[(size_t)(y0 + ff) * ELN + (x ^ 256)] = v;
        lmin = fminf(lmin, v);
        lmax = fmaxf(lmax, v);
    }
#pragma unroll
    for (int off = 16; off; off >>= 1) {
        lmin = fminf(lmin, __shfl_down_sync(0xFFFFFFFFu, lmin, off));
        lmax = fmaxf(lmax, __shfl_down_sync(0xFFFFFFFFu, lmax, off));
    }
    int wid = tid >> 5, lane = tid & 31;
    if (lane == 0) { smn[wid] = lmin; smx[wid] = lmax; }
    __syncthreads();
    if (tid == 0) {
        float mn = smn[0], mx = smx[0];
#pragma unroll
        for (int w = 1; w < 8; w++) { mn = fminf(mn, smn[w]); mx = fmaxf(mx, smx[w]); }
        atomicMin(&g_mm[2 * img],     fenc(mn));
        atomicMax(&g_mm[2 * img + 1], fenc(mx));
    }
}

// ---- K4: normalize + mask + MSE partial + concat outputs ----
__global__ __launch_bounds__(256) void k_out(const float* __restrict__ in0,
                                             const float* __restrict__ in1,
                                             float* __restrict__ out) {
    __shared__ float red[8];
    int r = blockIdx.x, b = blockIdx.y, tid = threadIdx.x;
    float mnI = fdec(g_mm[2 * b]),          mxI = fdec(g_mm[2 * b + 1]);
    float mnT = fdec(g_mm[2 * (b + BIMG)]), mxT = fdec(g_mm[2 * (b + BIMG) + 1]);
    float sI = 1.0f / (mxI - mnI + 1e-12f);
    float sT = 1.0f / (mxT - mnT + 1e-12f);
    const float* ain = g_ac + (size_t)b * IMG_PIX + (size_t)r * ELN;
    const float* atg = g_ac + (size_t)(b + BIMG) * IMG_PIX + (size_t)r * ELN;
    const float* rin = in0 + (size_t)b * IMG_PIX + (size_t)r * ELN;
    const float* rtg = in1 + (size_t)b * IMG_PIX + (size_t)r * ELN;
    float* o1 = out + 1 + (size_t)b * (ELN * 1024) + (size_t)r * 1024;
    float* o2 = o1 + (size_t)BIMG * (ELN * 1024);
    float dy = (float)(r - 256);
    float acc = 0.0f;
#pragma unroll
    for (int c = tid; c < ELN; c += 256) {
        float dx = (float)(c - 256);
        float mask = __expf(-(dx * dx + dy * dy) * (1.0f / 800.0f));
        float ia = (ain[c] - mnI) * sI * mask;
        float ta = (atg[c] - mnT) * sT * mask;
        float d = ia - ta;
        acc += d * d;
        o1[c] = rin[c];  o1[ELN + c] = ia;
        o2[c] = rtg[c];  o2[ELN + c] = ta;
    }
#pragma unroll
    for (int off = 16; off; off >>= 1)
        acc += __shfl_down_sync(0xFFFFFFFFu, acc, off);
    int wid = tid >> 5, lane = tid & 31;
    if (lane == 0) red[wid] = acc;
    __syncthreads();
    if (tid == 0) {
        float s = 0.0f;
#pragma unroll
        for (int w = 0; w < 8; w++) s += red[w];
        atomicAdd(&g_diff, (double)s);
    }
}

__global__ void k_fin(float* __restrict__ out) {
    out[0] = (float)(g_diff / (double)((size_t)BIMG * IMG_PIX));
}

extern "C" void kernel_launch(void* const* d_in, const int* in_sizes, int n_in,
                              void* d_out, int out_size) {
    const float* in0 = (const float*)d_in[0];   // input  (64,1,512,512)
    const float* in1 = (const float*)d_in[1];   // target (64,1,512,512)
    float* out = (float*)d_out;                 // [diff | input_and_ac | target_and_ac]

    k_init<<<1, 128>>>();
    k_fwd_x<<<dim3(128, NIMG), 256>>>(in0, in1);
    k_mid<<<dim3(128, NIMG), 256>>>();
    k_inv_x<<<dim3(128, NIMG), 256>>>();
    k_out<<<dim3(ELN, BIMG), 256>>>(in0, in1, out);
    k_fin<<<1, 1>>>(out);
}

// round 6
// speedup vs baseline: 2.5818x; 1.6972x over previous
#include <cuda_runtime.h>

#define ELN 512
#define NIMG 128
#define BIMG 64
#define IMG_PIX (ELN*ELN)
#define KXP 260              // padded half-spectrum width (257 used)
#define TWO_PI 6.28318530717958647692f

// Scratch (device globals; zero-initialized at load, padding never written)
__device__ float2 g_bufB[(size_t)NIMG * KXP * ELN];   // [img][kx 0..259][y]   ~136 MB
__device__ float2 g_bufA[(size_t)NIMG * ELN * KXP];   // [img][y'][kx 0..259]  ~136 MB
__device__ float  g_ac[(size_t)NIMG * IMG_PIX];
__device__ unsigned int g_mm[2 * NIMG];
__device__ double g_diff;

#define PAD(i) ((i) + ((i) >> 3))
#define SSZ 576   // 512 + 64 pad

// ---- monotone float <-> uint encoding for atomic min/max ----
__device__ __forceinline__ unsigned fenc(float f) {
    unsigned u = __float_as_uint(f);
    return (u & 0x80000000u) ? ~u : (u | 0x80000000u);
}
__device__ __forceinline__ float fdec(unsigned e) {
    return __uint_as_float((e & 0x80000000u) ? (e ^ 0x80000000u) : ~e);
}

__device__ __forceinline__ float2 cadd(float2 a, float2 b){ return make_float2(a.x+b.x, a.y+b.y); }
__device__ __forceinline__ float2 csub(float2 a, float2 b){ return make_float2(a.x-b.x, a.y-b.y); }
__device__ __forceinline__ float2 cmul(float2 a, float2 b){
    return make_float2(fmaf(a.x, b.x, -a.y*b.y), fmaf(a.x, b.y, a.y*b.x));
}
template<int SGN>
__device__ __forceinline__ float2 mul_si(float2 a){
    return (SGN > 0) ? make_float2(-a.y, a.x) : make_float2(a.y, -a.x);
}

// 8-point DFT in registers
template<int SGN>
__device__ __forceinline__ void dft8(float2* x){
    const float C = 0.70710678118654752440f;
    const float sg = (float)SGN;
    float2 F0 = cadd(x[0], x[4]), F1 = csub(x[0], x[4]);
    float2 G0 = cadd(x[2], x[6]), G1r = mul_si<SGN>(csub(x[2], x[6]));
    float2 H0 = cadd(x[1], x[5]), H1 = csub(x[1], x[5]);
    float2 I0 = cadd(x[3], x[7]), I1r = mul_si<SGN>(csub(x[3], x[7]));
    float2 E0 = cadd(F0, G0), E2 = csub(F0, G0);
    float2 E1 = cadd(F1, G1r), E3 = csub(F1, G1r);
    float2 O0 = cadd(H0, I0), O2 = csub(H0, I0);
    float2 O1 = cadd(H1, I1r), O3 = csub(H1, I1r);
    float2 W1O = make_float2(C*(O1.x - sg*O1.y), C*(O1.y + sg*O1.x));
    float2 W2O = make_float2(-sg*O2.y, sg*O2.x);
    float2 W3O = make_float2(C*(-O3.x - sg*O3.y), C*(sg*O3.x - O3.y));
    x[0] = cadd(E0, O0);  x[4] = csub(E0, O0);
    x[1] = cadd(E1, W1O); x[5] = csub(E1, W1O);
    x[2] = cadd(E2, W2O); x[6] = csub(E2, W2O);
    x[3] = cadd(E3, W3O); x[7] = csub(E3, W3O);
}

// One Stockham radix-8 stage. 64 threads per FFT (t = 0..63). L*M = 64.
template<int SGN, int L, int M>
__device__ __forceinline__ void stage8(const float2* src, float2* dst, int t){
    float2 x[8];
#pragma unroll
    for (int p = 0; p < 8; p++) x[p] = src[PAD(t + 64*p)];
    dft8<SGN>(x);
    int j = t / M, k = t - j*M;
    if (L > 1) {
        float ang = (float)SGN * (TWO_PI / (8.0f * (float)L)) * (float)j;
        float s, c; __sincosf(ang, &s, &c);
        float2 w = make_float2(c, s), wq = w;
        x[1] = cmul(x[1], wq);
#pragma unroll
        for (int q = 2; q < 8; q++) { wq = cmul(wq, w); x[q] = cmul(x[q], wq); }
    }
    int base = k + 8*j*M;
#pragma unroll
    for (int q = 0; q < 8; q++) dst[PAD(base + q*M)] = x[q];
}

// Full 512-pt FFT: input in s0, result in s1 (natural order, unscaled).
template<int SGN>
__device__ __forceinline__ void fft512_r8(float2* s0, float2* s1, int t){
    __syncthreads();
    stage8<SGN, 64, 1>(s0, s1, t);
    __syncthreads();
    stage8<SGN, 8, 8>(s1, s0, t);
    __syncthreads();
    stage8<SGN, 1, 64>(s0, s1, t);
    __syncthreads();
}

// ---- init accumulators (graph-replay safe) ----
__global__ void k_init() {
    int i = threadIdx.x;
    if (i < NIMG) { g_mm[2*i] = 0xFFFFFFFFu; g_mm[2*i + 1] = 0u; }
    if (i == 0) g_diff = 0.0;
}

// ---- K1: mf0 + forward x-FFT of 2 packed real rows per FFT.
//      Writes half-spectrum kx=0..256 transposed -> g_bufB [img][kx][y]. ----
__global__ __launch_bounds__(256) void k_fwd_x(const float* __restrict__ in0,
                                               const float* __restrict__ in1) {
    __shared__ float2 sm[2][4][SSZ];
    int tid = threadIdx.x, f = tid >> 6, t = tid & 63;
    int g = blockIdx.x, img = blockIdx.y;
    int y0 = g * 8;                 // 8 rows per block, 2 per FFT
    const float* src = (img < BIMG) ? in0 + (size_t)img * IMG_PIX
                                    : in1 + (size_t)(img - BIMG) * IMG_PIX;
    const float* ra = src + (size_t)(y0 + 2*f) * ELN;
    const float* rb = ra + ELN;
    float2* s0 = sm[0][f]; float2* s1 = sm[1][f];
#pragma unroll
    for (int p = 0; p < 8; p++) {
        float va = ra[t + 64*p], vb = rb[t + 64*p];
        s0[PAD(t + 64*p)] = make_float2(__expf(-8.0f * va * va),
                                        __expf(-8.0f * vb * vb));
    }
    fft512_r8<-1>(s0, s1, t);
    float2* ob = g_bufB + (size_t)img * KXP * ELN;
    for (int kx = tid; kx <= 256; kx += 256) {
        int m = (ELN - kx) & (ELN - 1);
        float4* o = (float4*)(ob + (size_t)kx * ELN + y0);
#pragma unroll
        for (int f2 = 0; f2 < 4; f2++) {
            float2 z  = sm[1][f2][PAD(kx)];
            float2 zm = sm[1][f2][PAD(m)];
            // F_A = (Z + conj(Zm))/2 ; F_B = (Z - conj(Zm))/(2i)
            o[f2] = make_float4(0.5f*(z.x + zm.x), 0.5f*(z.y - zm.y),
                                0.5f*(z.y + zm.y), 0.5f*(zm.x - z.x));
        }
    }
}

// ---- K2: fwd y-FFT + |.|^2 + inv y-FFT for kx columns 0..256 (padded 259).
//      Transposed write with y-roll -> g_bufA [img][y'][kx]. ----
__global__ __launch_bounds__(256) void k_mid() {
    __shared__ float2 sm[2][4][SSZ];
    int tid = threadIdx.x, f = tid >> 6, t = tid & 63;
    int g = blockIdx.x, img = blockIdx.y;
    int kx0 = g * 4;
    const float2* ib = g_bufB + (size_t)img * KXP * ELN + (size_t)(kx0 + f) * ELN;
    float2* s0 = sm[0][f]; float2* s1 = sm[1][f];
#pragma unroll
    for (int p = 0; p < 8; p++) s0[PAD(t + 64*p)] = ib[t + 64*p];
    fft512_r8<-1>(s0, s1, t);
#pragma unroll
    for (int p = 0; p < 8; p++) {
        float2 v = s1[PAD(t + 64*p)];
        s0[PAD(t + 64*p)] = make_float2(fmaf(v.x, v.x, v.y * v.y), 0.0f);
    }
    fft512_r8<1>(s0, s1, t);
    float2* ob = g_bufA + (size_t)img * ELN * KXP;
#pragma unroll
    for (int it = 0; it < 2; it++) {
        int y = tid + it * 256;
        float2 v0 = sm[1][0][PAD(y)], v1 = sm[1][1][PAD(y)];
        float2 v2 = sm[1][2][PAD(y)], v3 = sm[1][3][PAD(y)];
        float4* o = (float4*)(ob + (size_t)(y ^ 256) * KXP + kx0);
        o[0] = make_float4(v0.x, v0.y, v1.x, v1.y);
        o[1] = make_float4(v2.x, v2.y, v3.x, v3.y);
    }
}

// ---- K3: inverse x-FFT, 2 real output rows per FFT via Hermitian packing.
//      Applies x-roll, writes g_ac + per-image min/max. ----
__global__ __launch_bounds__(256) void k_inv_x() {
    __shared__ float2 sm[2][4][SSZ];
    __shared__ float smn[8], smx[8];
    int tid = threadIdx.x, f = tid >> 6, t = tid & 63;
    int g = blockIdx.x, img = blockIdx.y;
    int y0 = g * 8;
    const float2* Ga = g_bufA + (size_t)img * ELN * KXP + (size_t)(y0 + 2*f) * KXP;
    const float2* Gb = Ga + KXP;
    float2* s0 = sm[0][f]; float2* s1 = sm[1][f];
#pragma unroll
    for (int p = 0; p < 8; p++) {
        int kx = t + 64*p;
        float2 z;
        if (kx <= 256) {
            float2 a = Ga[kx], b = Gb[kx];
            z = make_float2(a.x - b.y, a.y + b.x);        // Ga + i*Gb
        } else {
            int m = ELN - kx;
            float2 a = Ga[m], b = Gb[m];
            z = make_float2(a.x + b.y, b.x - a.y);        // conj(Ga) + i*conj(Gb)
        }
        s0[PAD(kx)] = z;
    }
    fft512_r8<1>(s0, s1, t);

    float* ob = g_ac + (size_t)img * IMG_PIX;
    float lmin = 3.4e38f, lmax = -3.4e38f;
#pragma unroll
    for (int it = 0; it < 16; it++) {
        int idx = tid + it * 256;        // 0..4095 = 8 rows x 512
        int r8 = idx >> 9, x = idx & 511;
        float2 v2 = sm[1][r8 >> 1][PAD(x)];
        float v = (r8 & 1) ? v2.y : v2.x;
        ob[(size_t)(y0 + r8) * ELN + (x ^ 256)] = v;
        lmin = fminf(lmin, v);
        lmax = fmaxf(lmax, v);
    }
#pragma unroll
    for (int off = 16; off; off >>= 1) {
        lmin = fminf(lmin, __shfl_down_sync(0xFFFFFFFFu, lmin, off));
        lmax = fmaxf(lmax, __shfl_down_sync(0xFFFFFFFFu, lmax, off));
    }
    int wid = tid >> 5, lane = tid & 31;
    if (lane == 0) { smn[wid] = lmin; smx[wid] = lmax; }
    __syncthreads();
    if (tid == 0) {
        float mn = smn[0], mx = smx[0];
#pragma unroll
        for (int w = 1; w < 8; w++) { mn = fminf(mn, smn[w]); mx = fmaxf(mx, smx[w]); }
        atomicMin(&g_mm[2 * img],     fenc(mn));
        atomicMax(&g_mm[2 * img + 1], fenc(mx));
    }
}

// ---- K4: normalize + mask + MSE partial + concat outputs ----
__global__ __launch_bounds__(256) void k_out(const float* __restrict__ in0,
                                             const float* __restrict__ in1,
                                             float* __restrict__ out) {
    __shared__ float red[8];
    int r = blockIdx.x, b = blockIdx.y, tid = threadIdx.x;
    float mnI = fdec(g_mm[2 * b]),          mxI = fdec(g_mm[2 * b + 1]);
    float mnT = fdec(g_mm[2 * (b + BIMG)]), mxT = fdec(g_mm[2 * (b + BIMG) + 1]);
    float sI = 1.0f / (mxI - mnI + 1e-12f);
    float sT = 1.0f / (mxT - mnT + 1e-12f);
    const float* ain = g_ac + (size_t)b * IMG_PIX + (size_t)r * ELN;
    const float* atg = g_ac + (size_t)(b + BIMG) * IMG_PIX + (size_t)r * ELN;
    const float* rin = in0 + (size_t)b * IMG_PIX + (size_t)r * ELN;
    const float* rtg = in1 + (size_t)b * IMG_PIX + (size_t)r * ELN;
    float* o1 = out + 1 + (size_t)b * (ELN * 1024) + (size_t)r * 1024;
    float* o2 = o1 + (size_t)BIMG * (ELN * 1024);
    float dy = (float)(r - 256);
    float acc = 0.0f;
#pragma unroll
    for (int c = tid; c < ELN; c += 256) {
        float dx = (float)(c - 256);
        float mask = __expf(-(dx * dx + dy * dy) * (1.0f / 800.0f));
        float ia = (ain[c] - mnI) * sI * mask;
        float ta = (atg[c] - mnT) * sT * mask;
        float d = ia - ta;
        acc += d * d;
        o1[c] = rin[c];  o1[ELN + c] = ia;
        o2[c] = rtg[c];  o2[ELN + c] = ta;
    }
#pragma unroll
    for (int off = 16; off; off >>= 1)
        acc += __shfl_down_sync(0xFFFFFFFFu, acc, off);
    int wid = tid >> 5, lane = tid & 31;
    if (lane == 0) red[wid] = acc;
    __syncthreads();
    if (tid == 0) {
        float s = 0.0f;
#pragma unroll
        for (int w = 0; w < 8; w++) s += red[w];
        atomicAdd(&g_diff, (double)s);
    }
}

__global__ void k_fin(float* __restrict__ out) {
    out[0] = (float)(g_diff / (double)((size_t)BIMG * IMG_PIX));
}

extern "C" void kernel_launch(void* const* d_in, const int* in_sizes, int n_in,
                              void* d_out, int out_size) {
    const float* in0 = (const float*)d_in[0];   // input  (64,1,512,512)
    const float* in1 = (const float*)d_in[1];   // target (64,1,512,512)
    float* out = (float*)d_out;                 // [diff | input_and_ac | target_and_ac]

    k_init<<<1, 128>>>();
    k_fwd_x<<<dim3(64, NIMG), 256>>>(in0, in1);
    k_mid<<<dim3(65, NIMG), 256>>>();
    k_inv_x<<<dim3(64, NIMG), 256>>>();
    k_out<<<dim3(ELN, BIMG), 256>>>(in0, in1, out);
    k_fin<<<1, 1>>>(out);
}

// round 7
// speedup vs baseline: 3.3315x; 1.2904x over previous
#include <cuda_runtime.h>

#define ELN 512
#define NIMG 128
#define BIMG 64
#define IMG_PIX (ELN*ELN)
#define KXP 260              // padded half-spectrum width (257 used)
#define TWO_PI 6.28318530717958647692f

// Scratch (device globals; zero-initialized at load, padding never written)
__device__ float2 g_bufB[(size_t)NIMG * KXP * ELN];   // [img][kx 0..259][y]
__device__ float2 g_bufA[(size_t)NIMG * ELN * KXP];   // [img][y'][kx 0..259]
__device__ float  g_ac[(size_t)NIMG * IMG_PIX];
__device__ unsigned int g_mm[2 * NIMG];
__device__ double g_diff;

// XOR swizzle: conflict-free for both (t+64p) reads and (8t+q)/(k+64j+8q) writes
#define SW(i) ((i) ^ ((i) >> 3))

// ---- monotone float <-> uint encoding for atomic min/max ----
__device__ __forceinline__ unsigned fenc(float f) {
    unsigned u = __float_as_uint(f);
    return (u & 0x80000000u) ? ~u : (u | 0x80000000u);
}
__device__ __forceinline__ float fdec(unsigned e) {
    return __uint_as_float((e & 0x80000000u) ? (e ^ 0x80000000u) : ~e);
}

__device__ __forceinline__ float2 cadd(float2 a, float2 b){ return make_float2(a.x+b.x, a.y+b.y); }
__device__ __forceinline__ float2 csub(float2 a, float2 b){ return make_float2(a.x-b.x, a.y-b.y); }
__device__ __forceinline__ float2 cmul(float2 a, float2 b){
    return make_float2(fmaf(a.x, b.x, -a.y*b.y), fmaf(a.x, b.y, a.y*b.x));
}
template<int SGN>
__device__ __forceinline__ float2 mul_si(float2 a){
    return (SGN > 0) ? make_float2(-a.y, a.x) : make_float2(a.y, -a.x);
}

// 8-point DFT in registers
template<int SGN>
__device__ __forceinline__ void dft8(float2* x){
    const float C = 0.70710678118654752440f;
    const float sg = (float)SGN;
    float2 F0 = cadd(x[0], x[4]), F1 = csub(x[0], x[4]);
    float2 G0 = cadd(x[2], x[6]), G1r = mul_si<SGN>(csub(x[2], x[6]));
    float2 H0 = cadd(x[1], x[5]), H1 = csub(x[1], x[5]);
    float2 I0 = cadd(x[3], x[7]), I1r = mul_si<SGN>(csub(x[3], x[7]));
    float2 E0 = cadd(F0, G0), E2 = csub(F0, G0);
    float2 E1 = cadd(F1, G1r), E3 = csub(F1, G1r);
    float2 O0 = cadd(H0, I0), O2 = csub(H0, I0);
    float2 O1 = cadd(H1, I1r), O3 = csub(H1, I1r);
    float2 W1O = make_float2(C*(O1.x - sg*O1.y), C*(O1.y + sg*O1.x));
    float2 W2O = make_float2(-sg*O2.y, sg*O2.x);
    float2 W3O = make_float2(C*(-O3.x - sg*O3.y), C*(sg*O3.x - O3.y));
    x[0] = cadd(E0, O0);  x[4] = csub(E0, O0);
    x[1] = cadd(E1, W1O); x[5] = csub(E1, W1O);
    x[2] = cadd(E2, W2O); x[6] = csub(E2, W2O);
    x[3] = cadd(E3, W3O); x[7] = csub(E3, W3O);
}

template<int SGN>
__device__ __forceinline__ void twiddle(float2* x, int j, float invL8){
    float ang = (float)SGN * TWO_PI * invL8 * (float)j;
    float s, c; __sincosf(ang, &s, &c);
    float2 w = make_float2(c, s), wq = w;
    x[1] = cmul(x[1], wq);
#pragma unroll
    for (int q = 2; q < 8; q++) { wq = cmul(wq, w); x[q] = cmul(x[q], wq); }
}

// Stage 1 (L=64,M=1): x in regs -> dft8 -> twiddle(j=t) -> smem dst[8t+q]
template<int SGN>
__device__ __forceinline__ void stage1(float2* x, float2* dst, int t){
    dft8<SGN>(x);
    twiddle<SGN>(x, t, 1.0f / 512.0f);
#pragma unroll
    for (int q = 0; q < 8; q++) dst[SW(8*t + q)] = x[q];
}
// Stage 2 (L=8,M=8): read src[t+64p] -> dft8 -> twiddle(j=t>>3) -> dst[k+64j+8q]
template<int SGN>
__device__ __forceinline__ void stage2(const float2* src, float2* dst, int t){
    float2 x[8];
#pragma unroll
    for (int p = 0; p < 8; p++) x[p] = src[SW(t + 64*p)];
    dft8<SGN>(x);
    twiddle<SGN>(x, t >> 3, 1.0f / 64.0f);
    int base = (t & 7) + 64 * (t >> 3);
#pragma unroll
    for (int q = 0; q < 8; q++) dst[SW(base + 8*q)] = x[q];
}
// Stage 3 (L=1,M=64): read src[t+64p] -> dft8. Result x[q] = element (t+64q).
template<int SGN>
__device__ __forceinline__ void stage3(const float2* src, float2* x, int t){
#pragma unroll
    for (int p = 0; p < 8; p++) x[p] = src[SW(t + 64*p)];
    dft8<SGN>(x);
}

// ---- init accumulators (graph-replay safe) ----
__global__ void k_init() {
    int i = threadIdx.x;
    if (i < NIMG) { g_mm[2*i] = 0xFFFFFFFFu; g_mm[2*i + 1] = 0u; }
    if (i == 0) g_diff = 0.0;
}

// ---- K1: mf0 + forward x-FFT of 2 packed real rows per FFT.
//      Writes half-spectrum kx=0..256 transposed -> g_bufB [img][kx][y]. ----
__global__ __launch_bounds__(256) void k_fwd_x(const float* __restrict__ in0,
                                               const float* __restrict__ in1) {
    __shared__ float2 sA[4][ELN], sB[4][ELN];
    int tid = threadIdx.x, f = tid >> 6, t = tid & 63;
    int g = blockIdx.x, img = blockIdx.y;
    int y0 = g * 8;
    const float* src = (img < BIMG) ? in0 + (size_t)img * IMG_PIX
                                    : in1 + (size_t)(img - BIMG) * IMG_PIX;
    const float* ra = src + (size_t)(y0 + 2*f) * ELN;
    const float* rb = ra + ELN;
    float2 x[8];
#pragma unroll
    for (int p = 0; p < 8; p++) {
        float va = ra[t + 64*p], vb = rb[t + 64*p];
        x[p] = make_float2(__expf(-8.0f * va * va), __expf(-8.0f * vb * vb));
    }
    stage1<-1>(x, sA[f], t);
    __syncthreads();
    stage2<-1>(sA[f], sB[f], t);
    __syncthreads();
    stage3<-1>(sB[f], x, t);
#pragma unroll
    for (int q = 0; q < 8; q++) sA[f][SW(t + 64*q)] = x[q];
    __syncthreads();

    float2* ob = g_bufB + (size_t)img * KXP * ELN;
    for (int kx = tid; kx <= 256; kx += 256) {
        int m = (ELN - kx) & (ELN - 1);
        float4* o = (float4*)(ob + (size_t)kx * ELN + y0);
#pragma unroll
        for (int f2 = 0; f2 < 4; f2++) {
            float2 z  = sA[f2][SW(kx)];
            float2 zm = sA[f2][SW(m)];
            // F_A = (Z + conj(Zm))/2 ; F_B = (Z - conj(Zm))/(2i)
            o[f2] = make_float4(0.5f*(z.x + zm.x), 0.5f*(z.y - zm.y),
                                0.5f*(z.y + zm.y), 0.5f*(zm.x - z.x));
        }
    }
}

// ---- K2: fwd y-FFT + |.|^2 + inv y-FFT for kx columns 0..256 (padded 259).
//      Power feeds inverse with NO exchange (t+64q == t+64p pattern match).
//      Transposed write with y-roll -> g_bufA [img][y'][kx]. ----
__global__ __launch_bounds__(256) void k_mid() {
    __shared__ float2 sA[4][ELN], sB[4][ELN];
    int tid = threadIdx.x, f = tid >> 6, t = tid & 63;
    int g = blockIdx.x, img = blockIdx.y;
    int kx0 = g * 4;
    const float2* ib = g_bufB + (size_t)img * KXP * ELN + (size_t)(kx0 + f) * ELN;
    float2 x[8];
#pragma unroll
    for (int p = 0; p < 8; p++) x[p] = ib[t + 64*p];
    stage1<-1>(x, sA[f], t);
    __syncthreads();
    stage2<-1>(sA[f], sB[f], t);
    __syncthreads();
    stage3<-1>(sB[f], x, t);
    // |.|^2 in regs, then straight into inverse stage 1 (pattern matches)
#pragma unroll
    for (int p = 0; p < 8; p++)
        x[p] = make_float2(fmaf(x[p].x, x[p].x, x[p].y * x[p].y), 0.0f);
    stage1<1>(x, sA[f], t);
    __syncthreads();
    stage2<1>(sA[f], sB[f], t);
    __syncthreads();
    stage3<1>(sB[f], x, t);
#pragma unroll
    for (int q = 0; q < 8; q++) sA[f][SW(t + 64*q)] = x[q];
    __syncthreads();

    float2* ob = g_bufA + (size_t)img * ELN * KXP;
#pragma unroll
    for (int it = 0; it < 2; it++) {
        int y = tid + it * 256;
        float2 v0 = sA[0][SW(y)], v1 = sA[1][SW(y)];
        float2 v2 = sA[2][SW(y)], v3 = sA[3][SW(y)];
        float4* o = (float4*)(ob + (size_t)(y ^ 256) * KXP + kx0);
        o[0] = make_float4(v0.x, v0.y, v1.x, v1.y);
        o[1] = make_float4(v2.x, v2.y, v3.x, v3.y);
    }
}

// ---- K3: inverse x-FFT, 2 real output rows per FFT via Hermitian packing.
//      Applies x-roll, writes g_ac + per-image min/max. ----
__global__ __launch_bounds__(256) void k_inv_x() {
    __shared__ float2 sA[4][ELN], sB[4][ELN];
    __shared__ float smn[8], smx[8];
    int tid = threadIdx.x, f = tid >> 6, t = tid & 63;
    int g = blockIdx.x, img = blockIdx.y;
    int y0 = g * 8;
    const float2* Ga = g_bufA + (size_t)img * ELN * KXP + (size_t)(y0 + 2*f) * KXP;
    const float2* Gb = Ga + KXP;
    float2 x[8];
#pragma unroll
    for (int p = 0; p < 8; p++) {
        int kx = t + 64*p;
        if (kx <= 256) {
            float2 a = Ga[kx], b = Gb[kx];
            x[p] = make_float2(a.x - b.y, a.y + b.x);     // Ga + i*Gb
        } else {
            int m = ELN - kx;
            float2 a = Ga[m], b = Gb[m];
            x[p] = make_float2(a.x + b.y, b.x - a.y);     // conj(Ga) + i*conj(Gb)
        }
    }
    stage1<1>(x, sA[f], t);
    __syncthreads();
    stage2<1>(sA[f], sB[f], t);
    __syncthreads();
    stage3<1>(sB[f], x, t);
#pragma unroll
    for (int q = 0; q < 8; q++) sA[f][SW(t + 64*q)] = x[q];
    __syncthreads();

    float* ob = g_ac + (size_t)img * IMG_PIX;
    float lmin = 3.4e38f, lmax = -3.4e38f;
#pragma unroll
    for (int it = 0; it < 16; it++) {
        int idx = tid + it * 256;        // 0..4095 = 8 rows x 512
        int r8 = idx >> 9, xx = idx & 511;
        float2 v2 = sA[r8 >> 1][SW(xx)];
        float v = (r8 & 1) ? v2.y : v2.x;
        ob[(size_t)(y0 + r8) * ELN + (xx ^ 256)] = v;
        lmin = fminf(lmin, v);
        lmax = fmaxf(lmax, v);
    }
#pragma unroll
    for (int off = 16; off; off >>= 1) {
        lmin = fminf(lmin, __shfl_down_sync(0xFFFFFFFFu, lmin, off));
        lmax = fmaxf(lmax, __shfl_down_sync(0xFFFFFFFFu, lmax, off));
    }
    int wid = tid >> 5, lane = tid & 31;
    if (lane == 0) { smn[wid] = lmin; smx[wid] = lmax; }
    __syncthreads();
    if (tid == 0) {
        float mn = smn[0], mx = smx[0];
#pragma unroll
        for (int w = 1; w < 8; w++) { mn = fminf(mn, smn[w]); mx = fmaxf(mx, smx[w]); }
        atomicMin(&g_mm[2 * img],     fenc(mn));
        atomicMax(&g_mm[2 * img + 1], fenc(mx));
    }
}

// ---- K4: normalize + mask + MSE partial + concat outputs ----
__global__ __launch_bounds__(256) void k_out(const float* __restrict__ in0,
                                             const float* __restrict__ in1,
                                             float* __restrict__ out) {
    __shared__ float red[8];
    int r = blockIdx.x, b = blockIdx.y, tid = threadIdx.x;
    float mnI = fdec(g_mm[2 * b]),          mxI = fdec(g_mm[2 * b + 1]);
    float mnT = fdec(g_mm[2 * (b + BIMG)]), mxT = fdec(g_mm[2 * (b + BIMG) + 1]);
    float sI = 1.0f / (mxI - mnI + 1e-12f);
    float sT = 1.0f / (mxT - mnT + 1e-12f);
    const float* ain = g_ac + (size_t)b * IMG_PIX + (size_t)r * ELN;
    const float* atg = g_ac + (size_t)(b + BIMG) * IMG_PIX + (size_t)r * ELN;
    const float* rin = in0 + (size_t)b * IMG_PIX + (size_t)r * ELN;
    const float* rtg = in1 + (size_t)b * IMG_PIX + (size_t)r * ELN;
    float* o1 = out + 1 + (size_t)b * (ELN * 1024) + (size_t)r * 1024;
    float* o2 = o1 + (size_t)BIMG * (ELN * 1024);
    float dy = (float)(r - 256);
    float acc = 0.0f;
#pragma unroll
    for (int c = tid; c < ELN; c += 256) {
        float dx = (float)(c - 256);
        float mask = __expf(-(dx * dx + dy * dy) * (1.0f / 800.0f));
        float ia = (ain[c] - mnI) * sI * mask;
        float ta = (atg[c] - mnT) * sT * mask;
        float d = ia - ta;
        acc += d * d;
        o1[c] = rin[c];  o1[ELN + c] = ia;
        o2[c] = rtg[c];  o2[ELN + c] = ta;
    }
#pragma unroll
    for (int off = 16; off; off >>= 1)
        acc += __shfl_down_sync(0xFFFFFFFFu, acc, off);
    int wid = tid >> 5, lane = tid & 31;
    if (lane == 0) red[wid] = acc;
    __syncthreads();
    if (tid == 0) {
        float s = 0.0f;
#pragma unroll
        for (int w = 0; w < 8; w++) s += red[w];
        atomicAdd(&g_diff, (double)s);
    }
}

__global__ void k_fin(float* __restrict__ out) {
    out[0] = (float)(g_diff / (double)((size_t)BIMG * IMG_PIX));
}

extern "C" void kernel_launch(void* const* d_in, const int* in_sizes, int n_in,
                              void* d_out, int out_size) {
    const float* in0 = (const float*)d_in[0];   // input  (64,1,512,512)
    const float* in1 = (const float*)d_in[1];   // target (64,1,512,512)
    float* out = (float*)d_out;                 // [diff | input_and_ac | target_and_ac]

    k_init<<<1, 128>>>();
    k_fwd_x<<<dim3(64, NIMG), 256>>>(in0, in1);
    k_mid<<<dim3(65, NIMG), 256>>>();
    k_inv_x<<<dim3(64, NIMG), 256>>>();
    k_out<<<dim3(ELN, BIMG), 256>>>(in0, in1, out);
    k_fin<<<1, 1>>>(out);
}

// round 9
// speedup vs baseline: 4.0511x; 1.2160x over previous
#include <cuda_runtime.h>

#define ELN 512
#define NIMG 128
#define BIMG 64
#define IMG_PIX (ELN*ELN)
#define KXP 260              // padded half-spectrum width (257 used)
#define AROWS 258            // stored rows of rolled-AC spectrum (u = 0..257)
#define BAND_LO 136          // mask band: |u-256| <= 120
#define BAND_HI 376
#define TWO_PI 6.28318530717958647692f

// Scratch (device globals; zero-initialized at load, padding never written)
__device__ float2 g_bufB[(size_t)NIMG * KXP * ELN];    // [img][kx 0..259][y]
__device__ float2 g_bufA[(size_t)NIMG * AROWS * KXP];  // [img][u 0..257][kx]
__device__ float  g_ac[(size_t)NIMG * IMG_PIX];
__device__ unsigned int g_mm[2 * NIMG];
__device__ double g_diff;

// XOR swizzle: conflict-free for (t+64p) reads and (8t+q)/(k+64j+8q) writes
#define SW(i) ((i) ^ ((i) >> 3))

// ---- monotone float <-> uint encoding for atomic min/max ----
__device__ __forceinline__ unsigned fenc(float f) {
    unsigned u = __float_as_uint(f);
    return (u & 0x80000000u) ? ~u : (u | 0x80000000u);
}
__device__ __forceinline__ float fdec(unsigned e) {
    return __uint_as_float((e & 0x80000000u) ? (e ^ 0x80000000u) : ~e);
}

__device__ __forceinline__ float2 cadd(float2 a, float2 b){ return make_float2(a.x+b.x, a.y+b.y); }
__device__ __forceinline__ float2 csub(float2 a, float2 b){ return make_float2(a.x-b.x, a.y-b.y); }
__device__ __forceinline__ float2 cmul(float2 a, float2 b){
    return make_float2(fmaf(a.x, b.x, -a.y*b.y), fmaf(a.x, b.y, a.y*b.x));
}
template<int SGN>
__device__ __forceinline__ float2 mul_si(float2 a){
    return (SGN > 0) ? make_float2(-a.y, a.x) : make_float2(a.y, -a.x);
}

// 8-point DFT in registers
template<int SGN>
__device__ __forceinline__ void dft8(float2* x){
    const float C = 0.70710678118654752440f;
    const float sg = (float)SGN;
    float2 F0 = cadd(x[0], x[4]), F1 = csub(x[0], x[4]);
    float2 G0 = cadd(x[2], x[6]), G1r = mul_si<SGN>(csub(x[2], x[6]));
    float2 H0 = cadd(x[1], x[5]), H1 = csub(x[1], x[5]);
    float2 I0 = cadd(x[3], x[7]), I1r = mul_si<SGN>(csub(x[3], x[7]));
    float2 E0 = cadd(F0, G0), E2 = csub(F0, G0);
    float2 E1 = cadd(F1, G1r), E3 = csub(F1, G1r);
    float2 O0 = cadd(H0, I0), O2 = csub(H0, I0);
    float2 O1 = cadd(H1, I1r), O3 = csub(H1, I1r);
    float2 W1O = make_float2(C*(O1.x - sg*O1.y), C*(O1.y + sg*O1.x));
    float2 W2O = make_float2(-sg*O2.y, sg*O2.x);
    float2 W3O = make_float2(C*(-O3.x - sg*O3.y), C*(sg*O3.x - O3.y));
    x[0] = cadd(E0, O0);  x[4] = csub(E0, O0);
    x[1] = cadd(E1, W1O); x[5] = csub(E1, W1O);
    x[2] = cadd(E2, W2O); x[6] = csub(E2, W2O);
    x[3] = cadd(E3, W3O); x[7] = csub(E3, W3O);
}

template<int SGN>
__device__ __forceinline__ void twiddle(float2* x, int j, float invL8){
    float ang = (float)SGN * TWO_PI * invL8 * (float)j;
    float s, c; __sincosf(ang, &s, &c);
    float2 w = make_float2(c, s), wq = w;
    x[1] = cmul(x[1], wq);
#pragma unroll
    for (int q = 2; q < 8; q++) { wq = cmul(wq, w); x[q] = cmul(x[q], wq); }
}

// Stage 1 (L=64,M=1): x in regs -> dft8 -> twiddle(j=t) -> smem dst[8t+q]
template<int SGN>
__device__ __forceinline__ void stage1(float2* x, float2* dst, int t){
    dft8<SGN>(x);
    twiddle<SGN>(x, t, 1.0f / 512.0f);
#pragma unroll
    for (int q = 0; q < 8; q++) dst[SW(8*t + q)] = x[q];
}
// Stage 2 (L=8,M=8): read src[t+64p] -> dft8 -> twiddle(j=t>>3) -> dst[k+64j+8q]
template<int SGN>
__device__ __forceinline__ void stage2(const float2* src, float2* dst, int t){
    float2 x[8];
#pragma unroll
    for (int p = 0; p < 8; p++) x[p] = src[SW(t + 64*p)];
    dft8<SGN>(x);
    twiddle<SGN>(x, t >> 3, 1.0f / 64.0f);
    int base = (t & 7) + 64 * (t >> 3);
#pragma unroll
    for (int q = 0; q < 8; q++) dst[SW(base + 8*q)] = x[q];
}
// Stage 3 (L=1,M=64): read src[t+64p] -> dft8. Result x[q] = element (t+64q).
template<int SGN>
__device__ __forceinline__ void stage3(const float2* src, float2* x, int t){
#pragma unroll
    for (int p = 0; p < 8; p++) x[p] = src[SW(t + 64*p)];
    dft8<SGN>(x);
}

// ---- init accumulators (graph-replay safe) ----
__global__ void k_init() {
    int i = threadIdx.x;
    if (i < NIMG) { g_mm[2*i] = 0xFFFFFFFFu; g_mm[2*i + 1] = 0u; }
    if (i == 0) g_diff = 0.0;
}

// ---- K1: mf0 + forward x-FFT of 2 packed real rows per FFT.
//      Writes half-spectrum kx=0..256 transposed -> g_bufB [img][kx][y]. ----
__global__ __launch_bounds__(256) void k_fwd_x(const float* __restrict__ in0,
                                               const float* __restrict__ in1) {
    __shared__ float2 sA[4][ELN], sB[4][ELN];
    int tid = threadIdx.x, f = tid >> 6, t = tid & 63;
    int g = blockIdx.x, img = blockIdx.y;
    int y0 = g * 8;
    const float* src = (img < BIMG) ? in0 + (size_t)img * IMG_PIX
                                    : in1 + (size_t)(img - BIMG) * IMG_PIX;
    const float* ra = src + (size_t)(y0 + 2*f) * ELN;
    const float* rb = ra + ELN;
    float2 x[8];
#pragma unroll
    for (int p = 0; p < 8; p++) {
        float va = ra[t + 64*p], vb = rb[t + 64*p];
        x[p] = make_float2(__expf(-8.0f * va * va), __expf(-8.0f * vb * vb));
    }
    stage1<-1>(x, sA[f], t);
    __syncthreads();
    stage2<-1>(sA[f], sB[f], t);
    __syncthreads();
    stage3<-1>(sB[f], x, t);
#pragma unroll
    for (int q = 0; q < 8; q++) sA[f][SW(t + 64*q)] = x[q];
    __syncthreads();

    float2* ob = g_bufB + (size_t)img * KXP * ELN;
    for (int kx = tid; kx <= 256; kx += 256) {
        int m = (ELN - kx) & (ELN - 1);
        float4* o = (float4*)(ob + (size_t)kx * ELN + y0);
#pragma unroll
        for (int f2 = 0; f2 < 4; f2++) {
            float2 z  = sA[f2][SW(kx)];
            float2 zm = sA[f2][SW(m)];
            // F_A = (Z + conj(Zm))/2 ; F_B = (Z - conj(Zm))/(2i)
            o[f2] = make_float4(0.5f*(z.x + zm.x), 0.5f*(z.y - zm.y),
                                0.5f*(z.y + zm.y), 0.5f*(zm.x - z.x));
        }
    }
}

// ---- K2: fwd y-FFT + |.|^2 + inv y-FFT for kx columns 0..256 (padded 259).
//      Power feeds inverse with NO exchange. Transposed write with y-roll,
//      ONLY rows u = (y^256) <= 257 kept -> g_bufA [img][u][kx]. ----
__global__ __launch_bounds__(256) void k_mid() {
    __shared__ float2 sA[4][ELN], sB[4][ELN];
    int tid = threadIdx.x, f = tid >> 6, t = tid & 63;
    int g = blockIdx.x, img = blockIdx.y;
    int kx0 = g * 4;
    const float2* ib = g_bufB + (size_t)img * KXP * ELN + (size_t)(kx0 + f) * ELN;
    float2 x[8];
#pragma unroll
    for (int p = 0; p < 8; p++) x[p] = ib[t + 64*p];
    stage1<-1>(x, sA[f], t);
    __syncthreads();
    stage2<-1>(sA[f], sB[f], t);
    __syncthreads();
    stage3<-1>(sB[f], x, t);
    // |.|^2 in regs, straight into inverse stage 1 (pattern matches)
#pragma unroll
    for (int p = 0; p < 8; p++)
        x[p] = make_float2(fmaf(x[p].x, x[p].x, x[p].y * x[p].y), 0.0f);
    stage1<1>(x, sA[f], t);
    __syncthreads();
    stage2<1>(sA[f], sB[f], t);
    __syncthreads();
    stage3<1>(sB[f], x, t);
#pragma unroll
    for (int q = 0; q < 8; q++) sA[f][SW(t + 64*q)] = x[q];
    __syncthreads();

    float2* ob = g_bufA + (size_t)img * AROWS * KXP;
#pragma unroll
    for (int it = 0; it < 2; it++) {
        int y = tid + it * 256;
        int u = y ^ 256;                 // rolled row index
        if (u <= 257) {
            float2 v0 = sA[0][SW(y)], v1 = sA[1][SW(y)];
            float2 v2 = sA[2][SW(y)], v3 = sA[3][SW(y)];
            float4* o = (float4*)(ob + (size_t)u * KXP + kx0);
            o[0] = make_float4(v0.x, v0.y, v1.x, v1.y);
            o[1] = make_float4(v2.x, v2.y, v3.x, v3.y);
        }
    }
}

// ---- K3: inverse x-FFT of rows u=0..257 only (2 rows per FFT, Hermitian
//      packing). Full min/max from these rows (others are mirror duplicates).
//      Band rows [136,376] written to g_ac directly + via inversion mirror. ----
__global__ __launch_bounds__(256) void k_inv_x() {
    __shared__ float2 sA[4][ELN], sB[4][ELN];
    __shared__ float smn[8], smx[8];
    int tid = threadIdx.x, f = tid >> 6, t = tid & 63;
    int g = blockIdx.x, img = blockIdx.y;
    int p0 = min(g * 4, 125);            // pair index base (pairs 0..128)
    int u0 = p0 * 2;
    const float2* Ga = g_bufA + (size_t)img * AROWS * KXP + (size_t)(u0 + 2*f) * KXP;
    const float2* Gb = Ga + KXP;
    float2 x[8];
#pragma unroll
    for (int p = 0; p < 8; p++) {
        int kx = t + 64*p;
        if (kx <= 256) {
            float2 a = Ga[kx], b = Gb[kx];
            x[p] = make_float2(a.x - b.y, a.y + b.x);     // Ga + i*Gb
        } else {
            int m = ELN - kx;
            float2 a = Ga[m], b = Gb[m];
            x[p] = make_float2(a.x + b.y, b.x - a.y);     // conj(Ga) + i*conj(Gb)
        }
    }
    stage1<1>(x, sA[f], t);
    __syncthreads();
    stage2<1>(sA[f], sB[f], t);
    __syncthreads();
    stage3<1>(sB[f], x, t);
#pragma unroll
    for (int q = 0; q < 8; q++) sA[f][SW(t + 64*q)] = x[q];
    __syncthreads();

    float* ob = g_ac + (size_t)img * IMG_PIX;
    float lmin = 3.4e38f, lmax = -3.4e38f;
#pragma unroll
    for (int it = 0; it < 16; it++) {
        int idx = tid + it * 256;        // 0..4095 = 8 rows x 512
        int r8 = idx >> 9, xx = idx & 511;
        float2 v2 = sA[r8 >> 1][SW(xx)];
        float v = (r8 & 1) ? v2.y : v2.x;
        int u = u0 + r8;                 // 0..257
        int vcol = xx ^ 256;
        if (u >= BAND_LO) ob[(size_t)u * ELN + vcol] = v;       // u <= 257 < BAND_HI
        int um = (ELN - u) & (ELN - 1);  // mirror row
        if (um != u && um >= BAND_LO && um <= BAND_HI)
            ob[(size_t)um * ELN + ((ELN - vcol) & (ELN - 1))] = v;
        lmin = fminf(lmin, v);
        lmax = fmaxf(lmax, v);
    }
#pragma unroll
    for (int off = 16; off; off >>= 1) {
        lmin = fminf(lmin, __shfl_down_sync(0xFFFFFFFFu, lmin, off));
        lmax = fmaxf(lmax, __shfl_down_sync(0xFFFFFFFFu, lmax, off));
    }
    int wid = tid >> 5, lane = tid & 31;
    if (lane == 0) { smn[wid] = lmin; smx[wid] = lmax; }
    __syncthreads();
    if (tid == 0) {
        float mn = smn[0], mx = smx[0];
#pragma unroll
        for (int w = 1; w < 8; w++) { mn = fminf(mn, smn[w]); mx = fmaxf(mx, smx[w]); }
        atomicMin(&g_mm[2 * img],     fenc(mn));
        atomicMax(&g_mm[2 * img + 1], fenc(mx));
    }
}

// ---- K4: normalize + mask + MSE partial + concat outputs.
//      Outside the mask band the AC output is < 1.5e-8 -> write exact 0. ----
__global__ __launch_bounds__(256) void k_out(const float* __restrict__ in0,
                                             const float* __restrict__ in1,
                                             float* __restrict__ out) {
    __shared__ float red[8];
    int r = blockIdx.x, b = blockIdx.y, tid = threadIdx.x;
    const float* rin = in0 + (size_t)b * IMG_PIX + (size_t)r * ELN;
    const float* rtg = in1 + (size_t)b * IMG_PIX + (size_t)r * ELN;
    float* o1 = out + 1 + (size_t)b * (ELN * 1024) + (size_t)r * 1024;
    float* o2 = o1 + (size_t)BIMG * (ELN * 1024);

    if (r < BAND_LO || r > BAND_HI) {
#pragma unroll
        for (int c = tid; c < ELN; c += 256) {
            o1[c] = rin[c];  o1[ELN + c] = 0.0f;
            o2[c] = rtg[c];  o2[ELN + c] = 0.0f;
        }
        return;
    }

    float mnI = fdec(g_mm[2 * b]),          mxI = fdec(g_mm[2 * b + 1]);
    float mnT = fdec(g_mm[2 * (b + BIMG)]), mxT = fdec(g_mm[2 * (b + BIMG) + 1]);
    float sI = 1.0f / (mxI - mnI + 1e-12f);
    float sT = 1.0f / (mxT - mnT + 1e-12f);
    const float* ain = g_ac + (size_t)b * IMG_PIX + (size_t)r * ELN;
    const float* atg = g_ac + (size_t)(b + BIMG) * IMG_PIX + (size_t)r * ELN;
    float dy = (float)(r - 256);
    float acc = 0.0f;
#pragma unroll
    for (int c = tid; c < ELN; c += 256) {
        float dx = (float)(c - 256);
        float mask = __expf(-(dx * dx + dy * dy) * (1.0f / 800.0f));
        float ia = (ain[c] - mnI) * sI * mask;
        float ta = (atg[c] - mnT) * sT * mask;
        float d = ia - ta;
        acc += d * d;
        o1[c] = rin[c];  o1[ELN + c] = ia;
        o2[c] = rtg[c];  o2[ELN + c] = ta;
    }
#pragma unroll
    for (int off = 16; off; off >>= 1)
        acc += __shfl_down_sync(0xFFFFFFFFu, acc, off);
    int wid = tid >> 5, lane = tid & 31;
    if (lane == 0) red[wid] = acc;
    __syncthreads();
    if (tid == 0) {
        float s = 0.0f;
#pragma unroll
        for (int w = 0; w < 8; w++) s += red[w];
        atomicAdd(&g_diff, (double)s);
    }
}

__global__ void k_fin(float* __restrict__ out) {
    out[0] = (float)(g_diff / (double)((size_t)BIMG * IMG_PIX));
}

extern "C" void kernel_launch(void* const* d_in, const int* in_sizes, int n_in,
                              void* d_out, int out_size) {
    const float* in0 = (const float*)d_in[0];   // input  (64,1,512,512)
    const float* in1 = (const float*)d_in[1];   // target (64,1,512,512)
    float* out = (float*)d_out;                 // [diff | input_and_ac | target_and_ac]

    k_init<<<1, 128>>>();
    k_fwd_x<<<dim3(64, NIMG), 256>>>(in0, in1);
    k_mid<<<dim3(65, NIMG), 256>>>();
    k_inv_x<<<dim3(33, NIMG), 256>>>();
    k_out<<<dim3(ELN, BIMG), 256>>>(in0, in1, out);
    k_fin<<<1, 1>>>(out);
}